// round 9
// baseline (speedup 1.0000x reference)
#include <cuda_runtime.h>
#include <cuda_bf16.h>
#include <cstdint>
#include <cstddef>

// Problem constants
#define BATCH 128
#define HH    50
#define WW    9
#define LL    20
#define EE    256
#define OC    128
#define KTOT  1536          // 6 * 256 : k = (kh*2+kw)*256 + e
#define FCK   12288         // 128 * 24 * 4

// ---------------------------------------------------------------------------
// Device scratch. Split-bf16 representation: x ~= hi + lo, both bf16.
// ---------------------------------------------------------------------------
__device__ __nv_bfloat16 g_emb_hi[(size_t)BATCH * HH * WW * EE];  // 29.5 MB
__device__ __nv_bfloat16 g_emb_lo[(size_t)BATCH * HH * WW * EE];  // 29.5 MB
__device__ __nv_bfloat16 g_wb_hi[OC * KTOT];
__device__ __nv_bfloat16 g_wb_lo[OC * KTOT];
__device__ float g_v[FCK];
__device__ float g_c;
__device__ float g_acc[BATCH * 3];

// ---------------------------------------------------------------------------
// prep_w: conv_w [OC,E,3,2] f32 -> hi/lo bf16 pair, k=(kh*2+kw)*256+e
// ---------------------------------------------------------------------------
__global__ void prep_w_kernel(const float* __restrict__ conv_w) {
    int tid = blockIdx.x * blockDim.x + threadIdx.x;
    if (tid < OC * KTOT) {
        int oc = tid / KTOT, k = tid % KTOT;
        int khw = k >> 8, e = k & 255;
        int kh = khw >> 1, kw = khw & 1;
        float v = conv_w[((oc * EE + e) * 3 + kh) * 2 + kw];
        __nv_bfloat16 hi = __float2bfloat16(v);
        g_wb_hi[oc * KTOT + k] = hi;
        g_wb_lo[oc * KTOT + k] = __float2bfloat16(v - __bfloat162float(hi));
    }
}

// ---------------------------------------------------------------------------
// prep_v: fold fc1+fc2:  v[j] = sum_i fc2_w[i] * fc1_w[i][j]
//                        c    = fc2_b[0] + sum_i fc2_w[i] * fc1_b[i]
// ---------------------------------------------------------------------------
__global__ void prep_v_kernel(const float* __restrict__ fc1_w,
                              const float* __restrict__ fc1_b,
                              const float* __restrict__ fc2_w,
                              const float* __restrict__ fc2_b) {
    __shared__ float s_w2[128];
    int tid = threadIdx.x;
    if (tid < 128) s_w2[tid] = fc2_w[tid];
    __syncthreads();
    int j = blockIdx.x * blockDim.x + tid;
    if (j < FCK) {
        float s = 0.f;
        #pragma unroll 8
        for (int i = 0; i < 128; i++) s += s_w2[i] * __ldg(fc1_w + (size_t)i * FCK + j);
        g_v[j] = s;
    }
    if (blockIdx.x == 0 && tid == 0) {
        float c = fc2_b[0];
        #pragma unroll 8
        for (int i = 0; i < 128; i++) c += s_w2[i] * fc1_b[i];
        g_c = c;
    }
}

// ---------------------------------------------------------------------------
// gather: emb[b,h,w,e] = mean_l table[inputs[b,h,w,l]][e]  (f32 acc -> hi/lo)
// One block per cell (57600 blocks), 256 threads = 1 channel each.
// 20 independent full-line loads in flight per warp hide DRAM latency.
// ---------------------------------------------------------------------------
__global__ void gather_kernel(const int* __restrict__ inp,
                              const float* __restrict__ table) {
    __shared__ int s_idx[LL];
    int cell = blockIdx.x;
    int tid = threadIdx.x;
    if (tid < LL) s_idx[tid] = inp[cell * LL + tid];
    __syncthreads();
    float acc = 0.f;
    #pragma unroll
    for (int l = 0; l < LL; l++) {
        acc += __ldg(table + (size_t)s_idx[l] * EE + tid);
    }
    acc *= (1.0f / LL);
    __nv_bfloat16 hi = __float2bfloat16(acc);
    g_emb_hi[(size_t)cell * EE + tid] = hi;
    g_emb_lo[(size_t)cell * EE + tid] = __float2bfloat16(acc - __bfloat162float(hi));
}

// ---------------------------------------------------------------------------
// conv: implicit-GEMM bf16 mma.sync, tile M=128 (16 oh x 8 ow) x N=128 oc.
// Split-bf16 3-pass via K-stacking: 72 chunks = 24 x {hi*hi, hi*lo, lo*hi},
// all into one fp32 accumulator (effective precision ~2^-17).
// B tile is K-major (row = oc, contiguous k) -> plain ldmatrix, NO .trans:
// the mma B fragment needs consecutive-k at fixed n, which is exactly what
// non-trans ldmatrix delivers from K-contiguous rows (same as the A side).
// Epilogue fuses bias + 2x2 maxpool + relu + dot(v); one partial per
// (batch, m-tile) slot. No atomics.
// ---------------------------------------------------------------------------
__device__ __forceinline__ uint32_t smem_u32(const void* p) {
    return (uint32_t)__cvta_generic_to_shared(p);
}

__global__ __launch_bounds__(256, 2) void conv_kernel(const float* __restrict__ conv_b) {
    __shared__ __nv_bfloat16 As[128 * 72];   // 72 = 64 + 8 pad (conflict-free ldmatrix)
    __shared__ __nv_bfloat16 Bs[128 * 72];
    __shared__ float s_red[256];

    int mt  = blockIdx.x;        // 0..2   (oh tile)
    int b   = blockIdx.y;        // 0..127 (batch)
    int tid = threadIdx.x;
    int wid = tid >> 5;          // 0..7, warp owns m rows [wid*16, wid*16+16)
    int lane = tid & 31;
    int oh0 = mt * 16;

    float c[16][4];
    #pragma unroll
    for (int i = 0; i < 16; i++) {
        c[i][0] = 0.f; c[i][1] = 0.f; c[i][2] = 0.f; c[i][3] = 0.f;
    }

    for (int kc2 = 0; kc2 < 72; kc2++) {
        int pass = kc2 / 24;               // 0: hi*hi  1: hi*lo  2: lo*hi
        int kc   = kc2 - pass * 24;
        const __nv_bfloat16* Asrc = (pass == 2) ? g_emb_lo : g_emb_hi;
        const __nv_bfloat16* Bsrc = (pass == 1) ? g_wb_lo  : g_wb_hi;

        int khw = kc >> 2;
        int kh  = khw >> 1, kw = khw & 1;
        int e0  = (kc & 3) * 64;

        // A tile: im2col rows, 128 rows x 64 bf16 (contiguous e-slice per row)
        #pragma unroll
        for (int it = 0; it < 4; it++) {
            int idx = it * 256 + tid;
            int row = idx >> 3, seg = idx & 7;
            int oh  = oh0 + (row >> 3) + kh;         // <= 49
            int ow  = (row & 7) + kw;                // <= 8
            const uint4* src = (const uint4*)(Asrc +
                (((size_t)b * HH + oh) * WW + ow) * EE + e0 + seg * 8);
            *(uint4*)(As + row * 72 + seg * 8) = *src;
        }
        // B tile: 128 oc rows x 64 bf16
        #pragma unroll
        for (int it = 0; it < 4; it++) {
            int idx = it * 256 + tid;
            int row = idx >> 3, seg = idx & 7;
            const uint4* src = (const uint4*)(Bsrc + (size_t)row * KTOT + kc * 64 + seg * 8);
            *(uint4*)(Bs + row * 72 + seg * 8) = *src;
        }
        __syncthreads();

        #pragma unroll
        for (int ks = 0; ks < 4; ks++) {
            uint32_t a0, a1, a2, a3;
            uint32_t aaddr = smem_u32(As + (wid * 16 + (lane & 15)) * 72 + ks * 16 + (lane >> 4) * 8);
            asm volatile("ldmatrix.sync.aligned.m8n8.x4.shared.b16 {%0,%1,%2,%3}, [%4];"
                         : "=r"(a0), "=r"(a1), "=r"(a2), "=r"(a3) : "r"(aaddr));
            #pragma unroll
            for (int nt2 = 0; nt2 < 8; nt2++) {
                uint32_t b0, b1, b2, b3;
                uint32_t baddr = smem_u32(Bs + (nt2 * 16 + (lane & 15)) * 72 + ks * 16 + (lane >> 4) * 8);
                asm volatile("ldmatrix.sync.aligned.m8n8.x4.shared.b16 {%0,%1,%2,%3}, [%4];"
                             : "=r"(b0), "=r"(b1), "=r"(b2), "=r"(b3) : "r"(baddr));
                {   // n-tile 2*nt2 uses {b0, b2}  (k0-7, k8-15 at n0-7)
                    float* cc = c[2 * nt2];
                    asm volatile(
                        "mma.sync.aligned.m16n8k16.row.col.f32.bf16.bf16.f32 "
                        "{%0,%1,%2,%3}, {%4,%5,%6,%7}, {%8,%9}, {%0,%1,%2,%3};"
                        : "+f"(cc[0]), "+f"(cc[1]), "+f"(cc[2]), "+f"(cc[3])
                        : "r"(a0), "r"(a1), "r"(a2), "r"(a3), "r"(b0), "r"(b2));
                }
                {   // n-tile 2*nt2+1 uses {b1, b3}
                    float* cc = c[2 * nt2 + 1];
                    asm volatile(
                        "mma.sync.aligned.m16n8k16.row.col.f32.bf16.bf16.f32 "
                        "{%0,%1,%2,%3}, {%4,%5,%6,%7}, {%8,%9}, {%0,%1,%2,%3};"
                        : "+f"(cc[0]), "+f"(cc[1]), "+f"(cc[2]), "+f"(cc[3])
                        : "r"(a0), "r"(a1), "r"(a2), "r"(a3), "r"(b1), "r"(b3));
                }
            }
        }
        __syncthreads();
    }

    // Epilogue: bias + 2x2 maxpool + relu + dot with folded fc vector.
    // Frag layout: c[nt][0,1] at m-row g=lane>>2 (ohl = wid*2), cols n0,n0+1;
    //              c[nt][2,3] at m-row g+8     (ohl = wid*2+1).
    // -> max(c0,c2)/max(c1,c3) pools over oh. ow pairing = lanes l and l^4.
    float partial = 0.f;
    int ohp   = mt * 8 + wid;           // pooled oh: 0..23
    int g     = lane >> 2;              // ow within tile: 0..7
    int owp   = g >> 1;                 // pooled ow: 0..3
    bool active = (lane & 4) == 0;      // keep even-ow lane of each pool pair
    int ncol0 = (lane & 3) * 2;
    #pragma unroll
    for (int nt = 0; nt < 16; nt++) {
        int n0 = nt * 8 + ncol0;
        float t0 = fmaxf(c[nt][0], c[nt][2]);
        float t1 = fmaxf(c[nt][1], c[nt][3]);
        t0 = fmaxf(t0, __shfl_xor_sync(0xffffffffu, t0, 4));
        t1 = fmaxf(t1, __shfl_xor_sync(0xffffffffu, t1, 4));
        if (active) {
            float v0 = fmaxf(t0 + __ldg(conv_b + n0), 0.f);
            float v1 = fmaxf(t1 + __ldg(conv_b + n0 + 1), 0.f);
            partial += v0 * g_v[n0 * 96 + ohp * 4 + owp]
                     + v1 * g_v[(n0 + 1) * 96 + ohp * 4 + owp];
        }
    }
    s_red[tid] = partial;
    __syncthreads();
    #pragma unroll
    for (int s = 128; s > 0; s >>= 1) {
        if (tid < s) s_red[tid] += s_red[tid + s];
        __syncthreads();
    }
    if (tid == 0) g_acc[b * 3 + mt] = s_red[0];
}

// ---------------------------------------------------------------------------
// final: out[b] = sigmoid(sum of 3 partials + folded bias)
// ---------------------------------------------------------------------------
__global__ void final_kernel(float* __restrict__ out) {
    int b = threadIdx.x;
    if (b < BATCH) {
        float s = g_acc[b * 3] + g_acc[b * 3 + 1] + g_acc[b * 3 + 2] + g_c;
        out[b] = 1.f / (1.f + expf(-s));
    }
}

// ---------------------------------------------------------------------------
extern "C" void kernel_launch(void* const* d_in, const int* in_sizes, int n_in,
                              void* d_out, int out_size) {
    const int*   inputs    = (const int*)d_in[0];
    const float* emb_table = (const float*)d_in[1];
    const float* conv_w    = (const float*)d_in[2];
    const float* conv_b    = (const float*)d_in[3];
    const float* fc1_w     = (const float*)d_in[4];
    const float* fc1_b     = (const float*)d_in[5];
    const float* fc2_w     = (const float*)d_in[6];
    const float* fc2_b     = (const float*)d_in[7];
    float* out = (float*)d_out;

    prep_w_kernel<<<(OC * KTOT + 255) / 256, 256>>>(conv_w);
    prep_v_kernel<<<FCK / 256, 256>>>(fc1_w, fc1_b, fc2_w, fc2_b);
    gather_kernel<<<BATCH * HH * WW, 256>>>(inputs, emb_table);
    conv_kernel<<<dim3(3, BATCH), 256>>>(conv_b);
    final_kernel<<<1, 128>>>(out);
}

// round 10
// speedup vs baseline: 1.5757x; 1.5757x over previous
#include <cuda_runtime.h>
#include <cuda_bf16.h>
#include <cstdint>
#include <cstddef>

// Problem constants
#define BATCH 128
#define HH    50
#define WW    9
#define LL    20
#define EE    256
#define OC    128
#define KTOT  1536          // 6 * 256 : k = (kh*2+kw)*256 + e
#define FCK   12288         // 128 * 24 * 4

// ---------------------------------------------------------------------------
// Device scratch (static __device__ globals: the allowed scratch mechanism)
// ---------------------------------------------------------------------------
__device__ __nv_bfloat16 g_emb[(size_t)BATCH * HH * WW * EE];  // 29.5 MB
__device__ __nv_bfloat16 g_wb[OC * KTOT];                      // 384 KB
__device__ float g_v[FCK];
__device__ float g_c;
__device__ float g_acc[BATCH * 3];

// ---------------------------------------------------------------------------
// prep_w: conv_w [OC,E,3,2] f32 -> g_wb[oc][k] bf16 with k=(kh*2+kw)*256+e
// ---------------------------------------------------------------------------
__global__ void prep_w_kernel(const float* __restrict__ conv_w) {
    int tid = blockIdx.x * blockDim.x + threadIdx.x;
    if (tid < OC * KTOT) {
        int oc = tid / KTOT, k = tid % KTOT;
        int khw = k >> 8, e = k & 255;
        int kh = khw >> 1, kw = khw & 1;
        float v = conv_w[((oc * EE + e) * 3 + kh) * 2 + kw];
        g_wb[oc * KTOT + k] = __float2bfloat16(v);
    }
}

// ---------------------------------------------------------------------------
// prep_v: fold fc1+fc2:  v[j] = sum_i fc2_w[i] * fc1_w[i][j]
//                        c    = fc2_b[0] + sum_i fc2_w[i] * fc1_b[i]
// ---------------------------------------------------------------------------
__global__ void prep_v_kernel(const float* __restrict__ fc1_w,
                              const float* __restrict__ fc1_b,
                              const float* __restrict__ fc2_w,
                              const float* __restrict__ fc2_b) {
    __shared__ float s_w2[128];
    int tid = threadIdx.x;
    if (tid < 128) s_w2[tid] = fc2_w[tid];
    __syncthreads();
    int j = blockIdx.x * blockDim.x + tid;
    if (j < FCK) {
        float s = 0.f;
        #pragma unroll 8
        for (int i = 0; i < 128; i++) s += s_w2[i] * __ldg(fc1_w + (size_t)i * FCK + j);
        g_v[j] = s;
    }
    if (blockIdx.x == 0 && tid == 0) {
        float c = fc2_b[0];
        #pragma unroll 8
        for (int i = 0; i < 128; i++) c += s_w2[i] * fc1_b[i];
        g_c = c;
    }
}

// ---------------------------------------------------------------------------
// gather: emb[b,h,w,e] = mean_l table[inputs[b,h,w,l]][e]  (f32 acc -> bf16)
// One block per cell (57600 blocks), 256 threads = 1 channel each.
// 20 independent full-line loads in flight per warp hide DRAM latency.
// ---------------------------------------------------------------------------
__global__ void gather_kernel(const int* __restrict__ inp,
                              const float* __restrict__ table) {
    __shared__ int s_idx[LL];
    int cell = blockIdx.x;
    int tid = threadIdx.x;
    if (tid < LL) s_idx[tid] = inp[cell * LL + tid];
    __syncthreads();
    float acc = 0.f;
    #pragma unroll
    for (int l = 0; l < LL; l++) {
        acc += __ldg(table + (size_t)s_idx[l] * EE + tid);
    }
    g_emb[(size_t)cell * EE + tid] = __float2bfloat16(acc * (1.0f / LL));
}

// ---------------------------------------------------------------------------
// conv: implicit-GEMM bf16 mma.sync, tile M=128 (16 oh x 8 ow) x N=128 oc.
// Single-pass bf16 (validated: the R4-R8 error was a B-fragment .trans bug,
// not rounding; with it fixed the rounding-only error is ~1e-5 rel, 100x
// under the 1e-3 gate). K-loop: 24 chunks of 64.
// B tile is K-major (row = oc, contiguous k) -> plain ldmatrix, NO .trans.
// Epilogue fuses bias + 2x2 maxpool + relu + dot(v); one partial per
// (batch, m-tile) slot. No atomics.
// ---------------------------------------------------------------------------
__device__ __forceinline__ uint32_t smem_u32(const void* p) {
    return (uint32_t)__cvta_generic_to_shared(p);
}

__global__ __launch_bounds__(256, 2) void conv_kernel(const float* __restrict__ conv_b) {
    __shared__ __nv_bfloat16 As[128 * 72];   // 72 = 64 + 8 pad (conflict-free ldmatrix)
    __shared__ __nv_bfloat16 Bs[128 * 72];
    __shared__ float s_red[256];

    int mt  = blockIdx.x;        // 0..2   (oh tile)
    int b   = blockIdx.y;        // 0..127 (batch)
    int tid = threadIdx.x;
    int wid = tid >> 5;          // 0..7, warp owns m rows [wid*16, wid*16+16)
    int lane = tid & 31;
    int oh0 = mt * 16;

    float c[16][4];
    #pragma unroll
    for (int i = 0; i < 16; i++) {
        c[i][0] = 0.f; c[i][1] = 0.f; c[i][2] = 0.f; c[i][3] = 0.f;
    }

    for (int kc = 0; kc < 24; kc++) {
        int khw = kc >> 2;
        int kh  = khw >> 1, kw = khw & 1;
        int e0  = (kc & 3) * 64;

        // A tile: im2col rows, 128 rows x 64 bf16 (contiguous e-slice per row)
        #pragma unroll
        for (int it = 0; it < 4; it++) {
            int idx = it * 256 + tid;
            int row = idx >> 3, seg = idx & 7;
            int oh  = oh0 + (row >> 3) + kh;         // <= 49
            int ow  = (row & 7) + kw;                // <= 8
            const uint4* src = (const uint4*)(g_emb +
                (((size_t)b * HH + oh) * WW + ow) * EE + e0 + seg * 8);
            *(uint4*)(As + row * 72 + seg * 8) = *src;
        }
        // B tile: 128 oc rows x 64 bf16
        #pragma unroll
        for (int it = 0; it < 4; it++) {
            int idx = it * 256 + tid;
            int row = idx >> 3, seg = idx & 7;
            const uint4* src = (const uint4*)(g_wb + (size_t)row * KTOT + kc * 64 + seg * 8);
            *(uint4*)(Bs + row * 72 + seg * 8) = *src;
        }
        __syncthreads();

        #pragma unroll
        for (int ks = 0; ks < 4; ks++) {
            uint32_t a0, a1, a2, a3;
            uint32_t aaddr = smem_u32(As + (wid * 16 + (lane & 15)) * 72 + ks * 16 + (lane >> 4) * 8);
            asm volatile("ldmatrix.sync.aligned.m8n8.x4.shared.b16 {%0,%1,%2,%3}, [%4];"
                         : "=r"(a0), "=r"(a1), "=r"(a2), "=r"(a3) : "r"(aaddr));
            #pragma unroll
            for (int nt2 = 0; nt2 < 8; nt2++) {
                uint32_t b0, b1, b2, b3;
                uint32_t baddr = smem_u32(Bs + (nt2 * 16 + (lane & 15)) * 72 + ks * 16 + (lane >> 4) * 8);
                asm volatile("ldmatrix.sync.aligned.m8n8.x4.shared.b16 {%0,%1,%2,%3}, [%4];"
                             : "=r"(b0), "=r"(b1), "=r"(b2), "=r"(b3) : "r"(baddr));
                {   // n-tile 2*nt2 uses {b0, b2}  (k0-7, k8-15 at n0-7)
                    float* cc = c[2 * nt2];
                    asm volatile(
                        "mma.sync.aligned.m16n8k16.row.col.f32.bf16.bf16.f32 "
                        "{%0,%1,%2,%3}, {%4,%5,%6,%7}, {%8,%9}, {%0,%1,%2,%3};"
                        : "+f"(cc[0]), "+f"(cc[1]), "+f"(cc[2]), "+f"(cc[3])
                        : "r"(a0), "r"(a1), "r"(a2), "r"(a3), "r"(b0), "r"(b2));
                }
                {   // n-tile 2*nt2+1 uses {b1, b3}
                    float* cc = c[2 * nt2 + 1];
                    asm volatile(
                        "mma.sync.aligned.m16n8k16.row.col.f32.bf16.bf16.f32 "
                        "{%0,%1,%2,%3}, {%4,%5,%6,%7}, {%8,%9}, {%0,%1,%2,%3};"
                        : "+f"(cc[0]), "+f"(cc[1]), "+f"(cc[2]), "+f"(cc[3])
                        : "r"(a0), "r"(a1), "r"(a2), "r"(a3), "r"(b1), "r"(b3));
                }
            }
        }
        __syncthreads();
    }

    // Epilogue: bias + 2x2 maxpool + relu + dot with folded fc vector.
    // Frag layout: c[nt][0,1] at m-row g=lane>>2 (ohl = wid*2), cols n0,n0+1;
    //              c[nt][2,3] at m-row g+8     (ohl = wid*2+1).
    // -> max(c0,c2)/max(c1,c3) pools over oh. ow pairing = lanes l and l^4.
    float partial = 0.f;
    int ohp   = mt * 8 + wid;           // pooled oh: 0..23
    int g     = lane >> 2;              // ow within tile: 0..7
    int owp   = g >> 1;                 // pooled ow: 0..3
    bool active = (lane & 4) == 0;      // keep even-ow lane of each pool pair
    int ncol0 = (lane & 3) * 2;
    #pragma unroll
    for (int nt = 0; nt < 16; nt++) {
        int n0 = nt * 8 + ncol0;
        float t0 = fmaxf(c[nt][0], c[nt][2]);
        float t1 = fmaxf(c[nt][1], c[nt][3]);
        t0 = fmaxf(t0, __shfl_xor_sync(0xffffffffu, t0, 4));
        t1 = fmaxf(t1, __shfl_xor_sync(0xffffffffu, t1, 4));
        if (active) {
            float v0 = fmaxf(t0 + __ldg(conv_b + n0), 0.f);
            float v1 = fmaxf(t1 + __ldg(conv_b + n0 + 1), 0.f);
            partial += v0 * g_v[n0 * 96 + ohp * 4 + owp]
                     + v1 * g_v[(n0 + 1) * 96 + ohp * 4 + owp];
        }
    }
    s_red[tid] = partial;
    __syncthreads();
    #pragma unroll
    for (int s = 128; s > 0; s >>= 1) {
        if (tid < s) s_red[tid] += s_red[tid + s];
        __syncthreads();
    }
    if (tid == 0) g_acc[b * 3 + mt] = s_red[0];
}

// ---------------------------------------------------------------------------
// final: out[b] = sigmoid(sum of 3 partials + folded bias)
// ---------------------------------------------------------------------------
__global__ void final_kernel(float* __restrict__ out) {
    int b = threadIdx.x;
    if (b < BATCH) {
        float s = g_acc[b * 3] + g_acc[b * 3 + 1] + g_acc[b * 3 + 2] + g_c;
        out[b] = 1.f / (1.f + expf(-s));
    }
}

// ---------------------------------------------------------------------------
extern "C" void kernel_launch(void* const* d_in, const int* in_sizes, int n_in,
                              void* d_out, int out_size) {
    const int*   inputs    = (const int*)d_in[0];
    const float* emb_table = (const float*)d_in[1];
    const float* conv_w    = (const float*)d_in[2];
    const float* conv_b    = (const float*)d_in[3];
    const float* fc1_w     = (const float*)d_in[4];
    const float* fc1_b     = (const float*)d_in[5];
    const float* fc2_w     = (const float*)d_in[6];
    const float* fc2_b     = (const float*)d_in[7];
    float* out = (float*)d_out;

    prep_w_kernel<<<(OC * KTOT + 255) / 256, 256>>>(conv_w);
    prep_v_kernel<<<FCK / 256, 256>>>(fc1_w, fc1_b, fc2_w, fc2_b);
    gather_kernel<<<BATCH * HH * WW, 256>>>(inputs, emb_table);
    conv_kernel<<<dim3(3, BATCH), 256>>>(conv_b);
    final_kernel<<<1, 128>>>(out);
}